// round 13
// baseline (speedup 1.0000x reference)
#include <cuda_runtime.h>
#include <cstdint>

// OcrEmbedding: out[b,t,:] = sum_{s=0..3, id!=0} table[id[b,t,s], :]
// B=32, T=512, S=4, D=256, V=50000.
// d_in[0] = subtoken_ids (int32, B*T*S), d_in[1] = table (float32, V*D)
// Output: float32, B*T*D.
//
// Champion: one warp per token row, LDG.256 gathers (1KB/warp/subtoken),
// branch-free (all 4 loads issued back-to-back, id==0 masked by fmaf 0/1),
// 512-thread CTAs. Kernel runs at the measured L2 random-gather floor
// (~84MB @ ~7.9TB/s); rounds 1-12 established no path (TMA, cp.async,
// cache policy, width, occupancy) moves it.

#define BT (32 * 512)    // 16384 token rows

struct F8 { float v[8]; };

__device__ __forceinline__ F8 ldg256(const float* p) {
    F8 r;
    asm volatile("ld.global.nc.v8.f32 {%0,%1,%2,%3,%4,%5,%6,%7}, [%8];"
                 : "=f"(r.v[0]), "=f"(r.v[1]), "=f"(r.v[2]), "=f"(r.v[3]),
                   "=f"(r.v[4]), "=f"(r.v[5]), "=f"(r.v[6]), "=f"(r.v[7])
                 : "l"(p));
    return r;
}

__device__ __forceinline__ void stg256(float* p, const F8& r) {
    asm volatile("st.global.v8.f32 [%0], {%1,%2,%3,%4,%5,%6,%7,%8};"
                 :: "l"(p),
                    "f"(r.v[0]), "f"(r.v[1]), "f"(r.v[2]), "f"(r.v[3]),
                    "f"(r.v[4]), "f"(r.v[5]), "f"(r.v[6]), "f"(r.v[7])
                 : "memory");
}

__global__ __launch_bounds__(512) void ocr_embed_v8bf_kernel(
    const int* __restrict__ ids,          // [BT*4]
    const float* __restrict__ table,      // [V*256]
    float* __restrict__ out)              // [BT*256]
{
    const int gid  = blockIdx.x * 512 + threadIdx.x;
    const int row  = gid >> 5;            // one warp per token row
    const int off  = (gid & 31) * 8;      // 32B chunk within the 256-float row

    const int4 id = __ldg((const int4*)(ids + row * 4));  // warp-broadcast

    // Branch-free: id==0 is a valid (pad) row; always load, mask the add.
    const float m0 = (id.x != 0) ? 1.0f : 0.0f;
    const float m1 = (id.y != 0) ? 1.0f : 0.0f;
    const float m2 = (id.z != 0) ? 1.0f : 0.0f;
    const float m3 = (id.w != 0) ? 1.0f : 0.0f;

    // Four independent LDG.256, front-batched.
    const F8 a = ldg256(table + (size_t)id.x * 256 + off);
    const F8 b = ldg256(table + (size_t)id.y * 256 + off);
    const F8 c = ldg256(table + (size_t)id.z * 256 + off);
    const F8 d = ldg256(table + (size_t)id.w * 256 + off);

    F8 s;
    #pragma unroll
    for (int i = 0; i < 8; i++) {
        s.v[i] = fmaf(m0, a.v[i],
                 fmaf(m1, b.v[i],
                 fmaf(m2, c.v[i],
                      m3 * d.v[i])));
    }

    stg256(out + (size_t)row * 256 + off, s);
}

extern "C" void kernel_launch(void* const* d_in, const int* in_sizes, int n_in,
                              void* d_out, int out_size)
{
    const int*   ids   = (const int*)d_in[0];
    const float* table = (const float*)d_in[1];
    float*       out   = (float*)d_out;

    const int total   = BT * 32;          // one warp per row
    const int threads = 512;
    const int blocks  = total / threads;  // 1024

    ocr_embed_v8bf_kernel<<<blocks, threads>>>(ids, table, out);
}